// round 1
// baseline (speedup 1.0000x reference)
#include <cuda_runtime.h>
#include <cstdint>

// ---------------------------------------------------------------------------
// Problem shapes (fixed by setup_inputs): B=4, N=M=P=2048, NS=1024
//   d_in[0] pc1_0 [4,2048,3]   d_in[1] pc1_1 [4,1024,3]   d_in[2] pc1_3 [4,2048,1]
//   d_in[3] pc2   [4,2048,3]   d_in[4] pc3   [4,2048,3]
//   out [4,2048,2048] fp32
//
// out[b,n,m] = S + 0.5*dist(pc1_0[b,n], pc2[b,m])
// S = conf_loss + 0.5*cd(pc1_0||pc2 flat) + seed_cd(pc1_1||pc2 flat)
// ---------------------------------------------------------------------------

#define NPC2   8192      // B*M flattened
#define NPC10  8192      // B*N flattened
#define NPC11  4096      // B*NS flattened
#define SLOTS  5

__device__ int   g_min[SLOTS * 8192];   // min d^2, float bits stored as int (all >= 0)
__device__ float g_scal[3];             // [0]=cd, [1]=seed, [2]=conf

// -------------------------------- init ------------------------------------
__global__ void init_kernel() {
    int i = blockIdx.x * blockDim.x + threadIdx.x;
    if (i < SLOTS * 8192) g_min[i] = 0x7F7FFFFF;   // FLT_MAX bits
    if (i < 3) g_scal[i] = 0.0f;
}

// --------------------------- NN min-d^2 pass -------------------------------
// One thread per query point. Block loops over an R-chunk staged through smem
// (float4: x,y,z,|r|^2 — broadcast reads, conflict-free). Register-only min,
// one atomicMin(int) per (q, chunk).
#define TR 256
__global__ void nn_min_kernel(const float* __restrict__ Q,
                              const float* __restrict__ R,
                              int nr_chunk,
                              int qb_stride, int rb_stride,
                              int* __restrict__ gmin, int gmin_bstride)
{
    __shared__ float4 tile[TR];
    const int b = blockIdx.z;
    const float* Qb = Q + (size_t)b * qb_stride;
    const float* Rb = R + (size_t)b * rb_stride;

    const int q = blockIdx.x * blockDim.x + threadIdx.x;
    const float ax = Qb[3 * q + 0];
    const float ay = Qb[3 * q + 1];
    const float az = Qb[3 * q + 2];
    const float a2 = ax * ax + ay * ay + az * az;
    const float nax = -2.0f * ax, nay = -2.0f * ay, naz = -2.0f * az;

    float mn = __int_as_float(0x7F7FFFFF);
    const int rbase = blockIdx.y * nr_chunk;

    for (int t = 0; t < nr_chunk; t += TR) {
        const int ri = rbase + t + threadIdx.x;
        const float rx = Rb[3 * ri + 0];
        const float ry = Rb[3 * ri + 1];
        const float rz = Rb[3 * ri + 2];
        __syncthreads();   // previous tile fully consumed
        tile[threadIdx.x] = make_float4(rx, ry, rz, rx * rx + ry * ry + rz * rz);
        __syncthreads();
        #pragma unroll 8
        for (int k = 0; k < TR; k++) {
            const float4 r = tile[k];
            const float d2 = fmaf(nax, r.x, fmaf(nay, r.y, fmaf(naz, r.z, a2 + r.w)));
            mn = fminf(mn, d2);
        }
    }
    mn = fmaxf(mn, 0.0f);   // clip (also keeps int-compare atomicMin valid)
    atomicMin(&gmin[b * gmin_bstride + q], __float_as_int(mn));
}

// ------------------------------ finalize -----------------------------------
// 36864 elements total:
//  [0,16384)      slots 0,1 -> cd     (w = 1/8192 each)
//  [16384,24576)  slot 2    -> seed   (w = 1/8192)
//  [24576,28672)  slot 3    -> seed   (w = 1/4096, only 4096 valid)
//  [28672,36864)  slot 4    -> conf   ((pc1_3 - exp(-d))^2 / 8192)
#define N_FIN 36864
__global__ void finalize_kernel(const float* __restrict__ pc13)
{
    __shared__ float s[3];
    if (threadIdx.x < 3) s[threadIdx.x] = 0.0f;
    __syncthreads();

    const int i = blockIdx.x * blockDim.x + threadIdx.x;
    float val = 0.0f;
    int cat = 0;
    if (i < 16384) {
        cat = 0;
        val = sqrtf(__int_as_float(g_min[i])) * (1.0f / 8192.0f);
    } else if (i < 24576) {
        cat = 1;
        val = sqrtf(__int_as_float(g_min[i])) * (1.0f / 8192.0f);
    } else if (i < 28672) {
        cat = 1;
        const int q = i - 24576;
        val = sqrtf(__int_as_float(g_min[3 * 8192 + q])) * (1.0f / 4096.0f);
    } else {
        cat = 2;
        const int q = i - 28672;
        const float d  = sqrtf(__int_as_float(g_min[4 * 8192 + q]));
        const float gt = expf(-d);
        const float df = pc13[q] - gt;
        val = df * df * (1.0f / 8192.0f);
    }
    atomicAdd(&s[cat], val);
    __syncthreads();
    if (threadIdx.x < 3) atomicAdd(&g_scal[threadIdx.x], s[threadIdx.x]);
}

// --------------------------- output kernel ---------------------------------
// FFMA-only sqrt: bit-hack rsqrt + 2 Newton iterations (rel err ~5e-6).
// Avoids the MUFU pipe (rt 8/SMSP would cost ~126us for 16.8M sqrts).
__device__ __forceinline__ float fast_sqrt_ffma(float x) {
    float y = __uint_as_float(0x5f3759dfu - (__float_as_uint(x) >> 1));
    const float h = 0.5f * x;
    y = y * fmaf(-h * y, y, 1.5f);
    y = y * fmaf(-h * y, y, 1.5f);
    return x * y;   // exact 0 for x == 0 (y stays finite)
}

__global__ void out_kernel(const float* __restrict__ pc10,
                           const float* __restrict__ pc2,
                           float* __restrict__ out)
{
    const int bn = blockIdx.x;            // 0..8191 = b*2048 + n
    const int b  = bn >> 11;

    const float ax = pc10[3 * bn + 0];
    const float ay = pc10[3 * bn + 1];
    const float az = pc10[3 * bn + 2];
    const float a2 = ax * ax + ay * ay + az * az;
    const float nax = -2.0f * ax, nay = -2.0f * ay, naz = -2.0f * az;

    const float S = g_scal[2] + 0.5f * g_scal[0] + g_scal[1];

    const float4* R4 = (const float4*)(pc2 + (size_t)b * 2048 * 3);
    float4* o = (float4*)(out + (size_t)bn * 2048);

    #pragma unroll
    for (int half = 0; half < 2; half++) {
        // thread handles m = half*1024 + tid*4 .. +3  -> 12 floats = 3 float4
        const int base = half * 768 + threadIdx.x * 3;   // float4 index into R
        const float4 f0 = R4[base + 0];
        const float4 f1 = R4[base + 1];
        const float4 f2 = R4[base + 2];
        // unpack: (x0,y0,z0,x1)(y1,z1,x2,y2)(z2,x3,y3,z3)
        float d2[4];
        d2[0] = fmaf(nax, f0.x, fmaf(nay, f0.y, fmaf(naz, f0.z,
                 a2 + (f0.x * f0.x + f0.y * f0.y + f0.z * f0.z))));
        d2[1] = fmaf(nax, f0.w, fmaf(nay, f1.x, fmaf(naz, f1.y,
                 a2 + (f0.w * f0.w + f1.x * f1.x + f1.y * f1.y))));
        d2[2] = fmaf(nax, f1.z, fmaf(nay, f1.w, fmaf(naz, f2.x,
                 a2 + (f1.z * f1.z + f1.w * f1.w + f2.x * f2.x))));
        d2[3] = fmaf(nax, f2.y, fmaf(nay, f2.z, fmaf(naz, f2.w,
                 a2 + (f2.y * f2.y + f2.z * f2.z + f2.w * f2.w))));
        float4 res;
        res.x = fmaf(0.5f, fast_sqrt_ffma(fmaxf(d2[0], 0.0f)), S);
        res.y = fmaf(0.5f, fast_sqrt_ffma(fmaxf(d2[1], 0.0f)), S);
        res.z = fmaf(0.5f, fast_sqrt_ffma(fmaxf(d2[2], 0.0f)), S);
        res.w = fmaf(0.5f, fast_sqrt_ffma(fmaxf(d2[3], 0.0f)), S);
        o[half * 256 + threadIdx.x] = res;
    }
}

// ------------------------------ launcher -----------------------------------
extern "C" void kernel_launch(void* const* d_in, const int* in_sizes, int n_in,
                              void* d_out, int out_size)
{
    const float* pc10 = (const float*)d_in[0];
    const float* pc11 = (const float*)d_in[1];
    const float* pc13 = (const float*)d_in[2];
    const float* pc2  = (const float*)d_in[3];
    const float* pc3  = (const float*)d_in[4];
    float* out = (float*)d_out;

    int* gmin_ptr = nullptr;
    cudaGetSymbolAddress((void**)&gmin_ptr, g_min);

    // 1) init mins + accumulators
    init_kernel<<<(SLOTS * 8192 + 255) / 256, 256>>>();

    // 2) NN-min passes (all register-min, one atomicMin per (q, r-chunk))
    // cd dir1: per pc2 point, min over pc1_0   (slot 0)
    nn_min_kernel<<<dim3(32, 8, 1), 256>>>(pc2, pc10, 1024, 0, 0,
                                           gmin_ptr + 0 * 8192, 0);
    // cd dir2: per pc1_0 point, min over pc2   (slot 1)
    nn_min_kernel<<<dim3(32, 8, 1), 256>>>(pc10, pc2, 1024, 0, 0,
                                           gmin_ptr + 1 * 8192, 0);
    // seed dir1: per pc2 point, min over pc1_1 (slot 2)
    nn_min_kernel<<<dim3(32, 8, 1), 256>>>(pc2, pc11, 512, 0, 0,
                                           gmin_ptr + 2 * 8192, 0);
    // seed dir2: per pc1_1 point, min over pc2 (slot 3, 4096 queries)
    nn_min_kernel<<<dim3(16, 8, 1), 256>>>(pc11, pc2, 1024, 0, 0,
                                           gmin_ptr + 3 * 8192, 0);
    // conf: batched, per pc3[b,p] min over pc2[b,:] (slot 4)
    nn_min_kernel<<<dim3(8, 4, 4), 256>>>(pc3, pc2, 512,
                                          2048 * 3, 2048 * 3,
                                          gmin_ptr + 4 * 8192, 2048);

    // 3) reduce mins -> scalars (cd, seed, conf)
    finalize_kernel<<<N_FIN / 256, 256>>>(pc13);

    // 4) write out[b,n,m] = S + 0.5*dist
    out_kernel<<<8192, 256>>>(pc10, pc2, out);
}

// round 6
// speedup vs baseline: 1.4801x; 1.4801x over previous
#include <cuda_runtime.h>
#include <cstdint>

// ---------------------------------------------------------------------------
// Shapes (fixed): B=4, N=M=P=2048, NS=1024
//   d_in[0] pc1_0 [4,2048,3]  d_in[1] pc1_1 [4,1024,3]  d_in[2] pc1_3 [4,2048,1]
//   d_in[3] pc2   [4,2048,3]  d_in[4] pc3   [4,2048,3]  out [4,2048,2048] f32
//
// out[b,n,m] = S + 0.5*dist(pc1_0[b,n], pc2[b,m])
// S = conf + 0.5*cd(flat pc1_0||pc2) + seed_cd(flat pc1_1||pc2)
// ---------------------------------------------------------------------------

// partial min-d2 scratch: (chunk, query) per slot, no atomics needed
//  slot0: 16*8192  @0       cd dir1 (q=pc2,  R=pc1_0)
//  slot1: 16*8192  @131072  cd dir2 (q=pc1_0,R=pc2)
//  slot2:  8*8192  @262144  seed d1 (q=pc2,  R=pc1_1)
//  slot3: 16*4096  @327680  seed d2 (q=pc1_1,R=pc2)
//  slot4: 16*2048  @393216  conf    (per-b:  q=pc3,  R=pc2)
__device__ float g_part[425984];
__device__ float g_scal[3];    // [0]=cd [1]=seed [2]=conf

// ----------------------------- f32x2 helpers --------------------------------
__device__ __forceinline__ float2 f2fma(float2 a, float2 b, float2 c) {
    float2 r;
    asm("{.reg .b64 A,B,C,D;\n\t"
        "mov.b64 A,{%2,%3}; mov.b64 B,{%4,%5}; mov.b64 C,{%6,%7};\n\t"
        "fma.rn.f32x2 D,A,B,C;\n\t"
        "mov.b64 {%0,%1},D;}"
        : "=f"(r.x), "=f"(r.y)
        : "f"(a.x), "f"(a.y), "f"(b.x), "f"(b.y), "f"(c.x), "f"(c.y));
    return r;
}
__device__ __forceinline__ float2 f2mul(float2 a, float2 b) {
    float2 r;
    asm("{.reg .b64 A,B,D;\n\t"
        "mov.b64 A,{%2,%3}; mov.b64 B,{%4,%5};\n\t"
        "mul.rn.f32x2 D,A,B;\n\t"
        "mov.b64 {%0,%1},D;}"
        : "=f"(r.x), "=f"(r.y)
        : "f"(a.x), "f"(a.y), "f"(b.x), "f"(b.y));
    return r;
}
__device__ __forceinline__ float2 f2add(float2 a, float2 b) {
    float2 r;
    asm("{.reg .b64 A,B,D;\n\t"
        "mov.b64 A,{%2,%3}; mov.b64 B,{%4,%5};\n\t"
        "add.rn.f32x2 D,A,B;\n\t"
        "mov.b64 {%0,%1},D;}"
        : "=f"(r.x), "=f"(r.y)
        : "f"(a.x), "f"(a.y), "f"(b.x), "f"(b.y));
    return r;
}

// -------------------------------- init --------------------------------------
__global__ void init_kernel() {
    if (threadIdx.x < 3) g_scal[threadIdx.x] = 0.0f;
}

// --------------------------- fused NN min pass -------------------------------
// 832 blocks x 256 threads. Block = (task, 512-query block, 512-R chunk).
// 2 queries/thread. R chunk staged in smem packed per 2 points:
//   tile[2g]   = {x0, x1, y0, y1}
//   tile[2g+1] = {z0, z1, r2_0, r2_1}
// Accumulate min(r^2 - 2 a.r); epilogue adds a^2, clamps, writes partial.
__global__ void __launch_bounds__(256) nn_fused(const float* __restrict__ pc10,
                                                const float* __restrict__ pc11,
                                                const float* __restrict__ pc2,
                                                const float* __restrict__ pc3)
{
    __shared__ float4 tile[512];
    const int t = threadIdx.x;
    int l = blockIdx.x;

    const float* Q; const float* R; float* part; int qb, rc;
    if (l < 256)      { Q = pc2;  R = pc10; qb = l >> 4; rc = l & 15;
                        part = g_part +          rc * 8192 + qb * 512; }
    else if (l < 512) { l -= 256; Q = pc10; R = pc2;  qb = l >> 4; rc = l & 15;
                        part = g_part + 131072 + rc * 8192 + qb * 512; }
    else if (l < 640) { l -= 512; Q = pc2;  R = pc11; qb = l >> 3; rc = l & 7;
                        part = g_part + 262144 + rc * 8192 + qb * 512; }
    else if (l < 768) { l -= 640; Q = pc11; R = pc2;  qb = l >> 4; rc = l & 15;
                        part = g_part + 327680 + rc * 4096 + qb * 512; }
    else              { l -= 768; const int b = l >> 4; const int r = l & 15;
                        qb = r >> 2; rc = r & 3;
                        Q = pc3 + b * 6144; R = pc2 + b * 6144;
                        part = g_part + 393216 + (b * 4 + rc) * 2048 + qb * 512; }

    // ---- stage chunk: thread t packs R points (2t, 2t+1) of this chunk ----
    {
        const float* rp = R + (size_t)rc * 1536 + t * 6;   // 512 pts * 3
        const float2 p0 = *(const float2*)(rp + 0);   // x0 y0
        const float2 p1 = *(const float2*)(rp + 2);   // z0 x1
        const float2 p2 = *(const float2*)(rp + 4);   // y1 z1
        const float r20 = p0.x * p0.x + p0.y * p0.y + p1.x * p1.x;
        const float r21 = p1.y * p1.y + p2.x * p2.x + p2.y * p2.y;
        tile[2 * t]     = make_float4(p0.x, p1.y, p0.y, p2.x);
        tile[2 * t + 1] = make_float4(p1.x, p2.y, r20, r21);
    }

    // ---- two queries per thread ----
    const int q0 = qb * 512 + t;
    const int q1 = q0 + 256;
    const float ax0 = Q[3 * q0], ay0 = Q[3 * q0 + 1], az0 = Q[3 * q0 + 2];
    const float ax1 = Q[3 * q1], ay1 = Q[3 * q1 + 1], az1 = Q[3 * q1 + 2];
    const float a20 = ax0 * ax0 + ay0 * ay0 + az0 * az0;
    const float a21 = ax1 * ax1 + ay1 * ay1 + az1 * az1;
    const float2 nax0 = make_float2(-2.f * ax0, -2.f * ax0);
    const float2 nay0 = make_float2(-2.f * ay0, -2.f * ay0);
    const float2 naz0 = make_float2(-2.f * az0, -2.f * az0);
    const float2 nax1 = make_float2(-2.f * ax1, -2.f * ax1);
    const float2 nay1 = make_float2(-2.f * ay1, -2.f * ay1);
    const float2 naz1 = make_float2(-2.f * az1, -2.f * az1);

    float m0a = 3.0e38f, m0b = 3.0e38f, m1a = 3.0e38f, m1b = 3.0e38f;

    __syncthreads();

    #pragma unroll 8
    for (int g = 0; g < 256; g++) {
        const float4 A = tile[2 * g];
        const float4 Bq = tile[2 * g + 1];
        const float2 xx = make_float2(A.x, A.y);
        const float2 yy = make_float2(A.z, A.w);
        const float2 zz = make_float2(Bq.x, Bq.y);
        const float2 ww = make_float2(Bq.z, Bq.w);
        const float2 t0 = f2fma(nax0, xx, f2fma(nay0, yy, f2fma(naz0, zz, ww)));
        const float2 t1 = f2fma(nax1, xx, f2fma(nay1, yy, f2fma(naz1, zz, ww)));
        m0a = fminf(m0a, t0.x);  m0b = fminf(m0b, t0.y);
        m1a = fminf(m1a, t1.x);  m1b = fminf(m1b, t1.y);
    }

    part[t]       = fmaxf(fminf(m0a, m0b) + a20, 0.0f);
    part[t + 256] = fmaxf(fminf(m1a, m1b) + a21, 0.0f);
}

// ------------------------------ finalize ------------------------------------
// 36864 threads: reduce partial mins over chunks -> sqrt -> weighted sums.
__global__ void __launch_bounds__(256) finalize_kernel(const float* __restrict__ pc13)
{
    __shared__ float s[3];
    if (threadIdx.x < 3) s[threadIdx.x] = 0.0f;
    __syncthreads();

    const int i = blockIdx.x * 256 + threadIdx.x;
    float val; int cat;
    if (i < 8192) {                     // cd dir1
        float m = 3.0e38f;
        #pragma unroll
        for (int c = 0; c < 16; c++) m = fminf(m, g_part[c * 8192 + i]);
        val = sqrtf(m) * (1.0f / 8192.0f); cat = 0;
    } else if (i < 16384) {             // cd dir2
        const int q = i - 8192; float m = 3.0e38f;
        #pragma unroll
        for (int c = 0; c < 16; c++) m = fminf(m, g_part[131072 + c * 8192 + q]);
        val = sqrtf(m) * (1.0f / 8192.0f); cat = 0;
    } else if (i < 24576) {             // seed dir1
        const int q = i - 16384; float m = 3.0e38f;
        #pragma unroll
        for (int c = 0; c < 8; c++) m = fminf(m, g_part[262144 + c * 8192 + q]);
        val = sqrtf(m) * (1.0f / 8192.0f); cat = 1;
    } else if (i < 28672) {             // seed dir2
        const int q = i - 24576; float m = 3.0e38f;
        #pragma unroll
        for (int c = 0; c < 16; c++) m = fminf(m, g_part[327680 + c * 4096 + q]);
        val = sqrtf(m) * (1.0f / 4096.0f); cat = 1;
    } else {                            // confidence
        const int q = i - 28672;        // b*2048 + p
        const int b = q >> 11, p = q & 2047;
        float m = 3.0e38f;
        #pragma unroll
        for (int c = 0; c < 4; c++) m = fminf(m, g_part[393216 + (b * 4 + c) * 2048 + p]);
        const float gt = expf(-sqrtf(m));
        const float df = pc13[q] - gt;
        val = df * df * (1.0f / 8192.0f); cat = 2;
    }
    atomicAdd(&s[cat], val);
    __syncthreads();
    if (threadIdx.x < 3) atomicAdd(&g_scal[threadIdx.x], s[threadIdx.x]);
}

// ------------------------------ out kernel ----------------------------------
// 512 blocks x 256 threads. Block = (b, 16-row n chunk). Thread register-caches
// 8 pc2 points (4 packed groups), loops 16 n rows; all math f32x2-packed.
// NOTE: results accumulate into a proper float res[8] array (fully unrolled,
// register-resident) — NOT via pointer aliasing across float4 locals (R2 bug).
__global__ void __launch_bounds__(256) out_kernel(const float* __restrict__ pc10,
                                                  const float* __restrict__ pc2,
                                                  float* __restrict__ out)
{
    __shared__ float4 qs[32];            // per n: {nax,nax,nay,nay},{naz,naz,a2,a2}
    const int t = threadIdx.x;
    const int b  = blockIdx.x >> 7;
    const int nc = blockIdx.x & 127;
    const int nbase = b * 2048 + nc * 16;

    // ---- register cache: 8 pc2 points (m = 8t .. 8t+7) ----
    float F[24];
    {
        const float4* rp = (const float4*)(pc2 + (size_t)b * 6144 + t * 24);
        #pragma unroll
        for (int j = 0; j < 6; j++) {
            const float4 f = rp[j];
            F[4 * j] = f.x; F[4 * j + 1] = f.y; F[4 * j + 2] = f.z; F[4 * j + 3] = f.w;
        }
    }
    float2 Gx[4], Gy[4], Gz[4], Gw[4];
    #pragma unroll
    for (int g = 0; g < 4; g++) {
        const float x0 = F[6 * g], y0 = F[6 * g + 1], z0 = F[6 * g + 2];
        const float x1 = F[6 * g + 3], y1 = F[6 * g + 4], z1 = F[6 * g + 5];
        Gx[g] = make_float2(x0, x1);
        Gy[g] = make_float2(y0, y1);
        Gz[g] = make_float2(z0, z1);
        Gw[g] = make_float2(x0 * x0 + y0 * y0 + z0 * z0,
                            x1 * x1 + y1 * y1 + z1 * z1);
    }

    // ---- stage 16 queries ----
    if (t < 16) {
        const int n = nbase + t;
        const float x = pc10[3 * n], y = pc10[3 * n + 1], z = pc10[3 * n + 2];
        qs[2 * t]     = make_float4(-2.f * x, -2.f * x, -2.f * y, -2.f * y);
        qs[2 * t + 1] = make_float4(-2.f * z, -2.f * z,
                                    x * x + y * y + z * z, x * x + y * y + z * z);
    }
    const float S = g_scal[2] + 0.5f * g_scal[0] + g_scal[1];
    const float2 SS  = make_float2(S, S);
    const float2 C05 = make_float2(0.5f, 0.5f);
    const float2 C15 = make_float2(1.5f, 1.5f);
    const float2 CN5 = make_float2(-0.5f, -0.5f);
    __syncthreads();

    float* orow = out + (size_t)nbase * 2048 + 8 * t;
    #pragma unroll 4
    for (int n = 0; n < 16; n++) {
        const float4 qa = qs[2 * n];
        const float4 qb = qs[2 * n + 1];
        const float2 nx = make_float2(qa.x, qa.y);
        const float2 ny = make_float2(qa.z, qa.w);
        const float2 nz = make_float2(qb.x, qb.y);
        const float2 a2 = make_float2(qb.z, qb.w);
        float res[8];
        #pragma unroll
        for (int g = 0; g < 4; g++) {
            float2 d2 = f2fma(nx, Gx[g], f2fma(ny, Gy[g],
                        f2fma(nz, Gz[g], f2add(a2, Gw[g]))));
            d2.x = fmaxf(d2.x, 0.0f);
            d2.y = fmaxf(d2.y, 0.0f);
            float2 y;
            y.x = __uint_as_float(0x5f3759dfu - (__float_as_uint(d2.x) >> 1));
            y.y = __uint_as_float(0x5f3759dfu - (__float_as_uint(d2.y) >> 1));
            const float2 h = f2mul(CN5, d2);
            float2 hy = f2mul(h, y);
            float2 tt = f2fma(hy, y, C15);
            y = f2mul(y, tt);
            hy = f2mul(h, y);
            tt = f2fma(hy, y, C15);
            y = f2mul(y, tt);
            const float2 sd = f2mul(d2, y);       // sqrt(d2)
            const float2 rr = f2fma(C05, sd, SS);
            res[2 * g]     = rr.x;
            res[2 * g + 1] = rr.y;
        }
        ((float4*)orow)[0] = make_float4(res[0], res[1], res[2], res[3]);
        ((float4*)orow)[1] = make_float4(res[4], res[5], res[6], res[7]);
        orow += 2048;
    }
}

// ------------------------------ launcher ------------------------------------
extern "C" void kernel_launch(void* const* d_in, const int* in_sizes, int n_in,
                              void* d_out, int out_size)
{
    const float* pc10 = (const float*)d_in[0];
    const float* pc11 = (const float*)d_in[1];
    const float* pc13 = (const float*)d_in[2];
    const float* pc2  = (const float*)d_in[3];
    const float* pc3  = (const float*)d_in[4];
    float* out = (float*)d_out;

    init_kernel<<<1, 32>>>();
    nn_fused<<<832, 256>>>(pc10, pc11, pc2, pc3);
    finalize_kernel<<<144, 256>>>(pc13);
    out_kernel<<<512, 256>>>(pc10, pc2, out);
}